// round 13
// baseline (speedup 1.0000x reference)
#include <cuda_runtime.h>

#define BDIM 1024
#define TDIM 4096
#define WSZ 10
#define HID 32
#define NPOS (TDIM - WSZ)            /* 4086 */
#define THREADS 128
#define PAIRS 2
#define POS_PER_CTA (THREADS * PAIRS * 2) /* 512 */
#define HALF (THREADS * PAIRS)       /* 256 */

typedef unsigned long long ull;

__constant__ __align__(16) float cW1[WSZ * HID];   // [w][j]
__constant__ __align__(16) float cW2[HID * HID];   // [k][j]
__constant__ __align__(16) float cW3[HID];
__constant__ __align__(16) float cb1[HID];
__constant__ __align__(16) float cb2[HID];
__constant__ __align__(16) float cb3s[4];

__device__ __forceinline__ ull pk2(float lo, float hi) {
    ull r;
    asm("mov.b64 %0, {%1, %2};" : "=l"(r) : "f"(lo), "f"(hi));
    return r;
}
__device__ __forceinline__ void upk2(ull p, float& lo, float& hi) {
    asm("mov.b64 {%0, %1}, %2;" : "=f"(lo), "=f"(hi) : "l"(p));
}
__device__ __forceinline__ ull fma2(ull a, ull b, ull c) {
    ull d;
    asm("fma.rn.f32x2 %0, %1, %2, %3;" : "=l"(d) : "l"(a), "l"(b), "l"(c));
    return d;
}

__global__ __launch_bounds__(THREADS, 3)
void hurst_mlp_kernel(const float* __restrict__ returns,
                      float* __restrict__ out)
{
    __shared__ __align__(16) float sxs[POS_PER_CTA + WSZ + 6];

    const int tid = threadIdx.x;
    const int row = blockIdx.y;
    const int p0  = blockIdx.x * POS_PER_CTA;

    const float* xrow = returns + (long)row * TDIM;
    for (int i = tid; i < POS_PER_CTA + WSZ; i += THREADS) {
        int t = p0 + i;
        sxs[i] = (t < TDIM) ? xrow[t] : 0.0f;
    }
    const float bb3 = cb3s[0];
    __syncthreads();

    #pragma unroll 1
    for (int r = 0; r < PAIRS; r++) {
        const int plA = tid + r * THREADS;
        const int plB = plA + HALF;
        const int pA  = p0 + plA;
        const int pB  = p0 + plB;

        // ---- layer 1 (packed f32x2 over j), weights from constant port
        ull h1A[HID/2], h1B[HID/2];
        {
            const ulonglong2* bp = (const ulonglong2*)cb1;
            #pragma unroll
            for (int q = 0; q < HID/4; q++) {
                ulonglong2 bv = bp[q];
                h1A[2*q]   = bv.x;  h1A[2*q+1] = bv.y;
                h1B[2*q]   = bv.x;  h1B[2*q+1] = bv.y;
            }
        }
        #pragma unroll
        for (int w = 0; w < WSZ; w++) {
            const float xA = sxs[plA + w];
            const float xB = sxs[plB + w];
            const ull xpA = pk2(xA, xA);
            const ull xpB = pk2(xB, xB);
            const ulonglong2* wrow = (const ulonglong2*)(cW1 + w * HID);
            #pragma unroll
            for (int q = 0; q < HID/4; q++) {
                const ulonglong2 wv = wrow[q];
                h1A[2*q]   = fma2(xpA, wv.x, h1A[2*q]);
                h1A[2*q+1] = fma2(xpA, wv.y, h1A[2*q+1]);
                h1B[2*q]   = fma2(xpB, wv.x, h1B[2*q]);
                h1B[2*q+1] = fma2(xpB, wv.y, h1B[2*q+1]);
            }
        }

        // unpack + relu once
        float vA[HID], vB[HID];
        #pragma unroll
        for (int q = 0; q < HID/2; q++) {
            float lo, hi;
            upk2(h1A[q], lo, hi);
            vA[2*q]   = fmaxf(lo, 0.0f);
            vA[2*q+1] = fmaxf(hi, 0.0f);
            upk2(h1B[q], lo, hi);
            vB[2*q]   = fmaxf(lo, 0.0f);
            vB[2*q+1] = fmaxf(hi, 0.0f);
        }

        // ---- layers 2+3 fused, 2 chunks of 16 outputs, packed f32x2
        float zA = bb3, zB = bb3;
        #pragma unroll 1
        for (int c = 0; c < 2; c++) {
            ull accA[8], accB[8];
            {
                const ulonglong2* bp = (const ulonglong2*)(cb2 + c * 16);
                #pragma unroll
                for (int q = 0; q < 4; q++) {
                    ulonglong2 bv = bp[q];
                    accA[2*q]   = bv.x;  accA[2*q+1] = bv.y;
                    accB[2*q]   = bv.x;  accB[2*q+1] = bv.y;
                }
            }

            #pragma unroll
            for (int k = 0; k < HID; k++) {
                const ull vpA = pk2(vA[k], vA[k]);
                const ull vpB = pk2(vB[k], vB[k]);
                const ulonglong2* w2r = (const ulonglong2*)(cW2 + k * HID + c * 16);
                #pragma unroll
                for (int q = 0; q < 4; q++) {
                    const ulonglong2 wv = w2r[q];
                    accA[2*q]   = fma2(vpA, wv.x, accA[2*q]);
                    accA[2*q+1] = fma2(vpA, wv.y, accA[2*q+1]);
                    accB[2*q]   = fma2(vpB, wv.x, accB[2*q]);
                    accB[2*q+1] = fma2(vpB, wv.y, accB[2*q+1]);
                }
            }

            const float* w3c = cW3 + c * 16;
            #pragma unroll
            for (int q = 0; q < 8; q++) {
                float lo, hi;
                upk2(accA[q], lo, hi);
                zA += fmaxf(lo, 0.0f) * w3c[2*q];
                zA += fmaxf(hi, 0.0f) * w3c[2*q+1];
                upk2(accB[q], lo, hi);
                zB += fmaxf(lo, 0.0f) * w3c[2*q];
                zB += fmaxf(hi, 0.0f) * w3c[2*q+1];
            }
        }

        const float oA = 0.5f / (1.0f + __expf(-zA));
        const float oB = 0.5f / (1.0f + __expf(-zB));

        if (pA < NPOS) {
            out[(long)row * TDIM + WSZ + pA] = oA;
            if (pA == 0) {
                #pragma unroll
                for (int c = 0; c < WSZ; c++)
                    out[(long)row * TDIM + c] = oA;
            }
        }
        if (pB < NPOS) {
            out[(long)row * TDIM + WSZ + pB] = oB;
        }
    }
}

extern "C" void kernel_launch(void* const* d_in, const int* in_sizes, int n_in,
                              void* d_out, int out_size)
{
    const float* returns = (const float*)d_in[0];
    float* out           = (float*)d_out;

    // Stage weights into constant memory (async D2D, graph-capturable, no allocs)
    cudaMemcpyToSymbolAsync(cW1,  d_in[1], WSZ * HID * sizeof(float), 0, cudaMemcpyDeviceToDevice, 0);
    cudaMemcpyToSymbolAsync(cb1,  d_in[2], HID * sizeof(float),       0, cudaMemcpyDeviceToDevice, 0);
    cudaMemcpyToSymbolAsync(cW2,  d_in[3], HID * HID * sizeof(float), 0, cudaMemcpyDeviceToDevice, 0);
    cudaMemcpyToSymbolAsync(cb2,  d_in[4], HID * sizeof(float),       0, cudaMemcpyDeviceToDevice, 0);
    cudaMemcpyToSymbolAsync(cW3,  d_in[5], HID * sizeof(float),       0, cudaMemcpyDeviceToDevice, 0);
    cudaMemcpyToSymbolAsync(cb3s, d_in[6], 1 * sizeof(float),         0, cudaMemcpyDeviceToDevice, 0);

    dim3 grid((NPOS + POS_PER_CTA - 1) / POS_PER_CTA, BDIM); // (8, 1024)
    hurst_mlp_kernel<<<grid, THREADS>>>(returns, out);
}

// round 14
// speedup vs baseline: 4.0880x; 4.0880x over previous
#include <cuda_runtime.h>

#define BDIM 1024
#define TDIM 4096
#define WSZ 10
#define HID 32
#define NPOS (TDIM - WSZ)            /* 4086 */
#define THREADS 128
#define NS 4                          /* position streams per thread */
#define POS_PER_CTA (THREADS * NS)    /* 512 */

typedef unsigned long long ull;

__device__ __forceinline__ ull pk2(float lo, float hi) {
    ull r;
    asm("mov.b64 %0, {%1, %2};" : "=l"(r) : "f"(lo), "f"(hi));
    return r;
}
__device__ __forceinline__ void upk2(ull p, float& lo, float& hi) {
    asm("mov.b64 {%0, %1}, %2;" : "=f"(lo), "=f"(hi) : "l"(p));
}
__device__ __forceinline__ ull fma2(ull a, ull b, ull c) {
    ull d;
    asm("fma.rn.f32x2 %0, %1, %2, %3;" : "=l"(d) : "l"(a), "l"(b), "l"(c));
    return d;
}

__global__ __launch_bounds__(THREADS, 2)
void hurst_mlp_kernel(const float* __restrict__ returns,
                      const float* __restrict__ W1, const float* __restrict__ b1,
                      const float* __restrict__ W2, const float* __restrict__ b2,
                      const float* __restrict__ W3, const float* __restrict__ b3,
                      float* __restrict__ out)
{
    __shared__ __align__(16) float sW1[WSZ * HID];   // [w][j]
    __shared__ __align__(16) float sW2[HID * HID];   // [k][j]
    __shared__ __align__(16) float sW3[HID];
    __shared__ __align__(16) float sb1[HID];
    __shared__ __align__(16) float sb2[HID];
    __shared__ __align__(16) float sxs[POS_PER_CTA + WSZ + 6];

    const int tid = threadIdx.x;
    const int row = blockIdx.y;
    const int p0  = blockIdx.x * POS_PER_CTA;

    for (int i = tid; i < WSZ * HID; i += THREADS) sW1[i] = W1[i];
    for (int i = tid; i < HID * HID; i += THREADS) sW2[i] = W2[i];
    if (tid < HID) { sW3[tid] = W3[tid]; sb1[tid] = b1[tid]; sb2[tid] = b2[tid]; }

    const float* xrow = returns + (long)row * TDIM;
    for (int i = tid; i < POS_PER_CTA + WSZ; i += THREADS) {
        int t = p0 + i;
        sxs[i] = (t < TDIM) ? xrow[t] : 0.0f;
    }
    const float bb3 = b3[0];
    __syncthreads();

    // ---- layer 1: 4 streams share every W1 load (packed f32x2 over j)
    ull h[NS][HID/2];
    {
        const ulonglong2* bp = (const ulonglong2*)sb1;
        #pragma unroll
        for (int q = 0; q < HID/4; q++) {
            const ulonglong2 bv = bp[q];
            #pragma unroll
            for (int s = 0; s < NS; s++) { h[s][2*q] = bv.x; h[s][2*q+1] = bv.y; }
        }
    }
    #pragma unroll
    for (int w = 0; w < WSZ; w++) {
        ull xp[NS];
        #pragma unroll
        for (int s = 0; s < NS; s++) {
            const float xv = sxs[tid + s * THREADS + w];
            xp[s] = pk2(xv, xv);
        }
        const ulonglong2* wrow = (const ulonglong2*)(sW1 + w * HID);
        #pragma unroll
        for (int q = 0; q < HID/4; q++) {
            const ulonglong2 wv = wrow[q];
            #pragma unroll
            for (int s = 0; s < NS; s++) {
                h[s][2*q]   = fma2(xp[s], wv.x, h[s][2*q]);
                h[s][2*q+1] = fma2(xp[s], wv.y, h[s][2*q+1]);
            }
        }
    }

    // unpack + relu once; h dies, v takes its registers
    float v[NS][HID];
    #pragma unroll
    for (int s = 0; s < NS; s++) {
        #pragma unroll
        for (int q = 0; q < HID/2; q++) {
            float lo, hi;
            upk2(h[s][q], lo, hi);
            v[s][2*q]   = fmaxf(lo, 0.0f);
            v[s][2*q+1] = fmaxf(hi, 0.0f);
        }
    }

    // ---- layers 2+3 fused: 2 chunks of 16 outputs, 4 streams share all W2/W3 loads
    float z[NS];
    #pragma unroll
    for (int s = 0; s < NS; s++) z[s] = bb3;

    #pragma unroll 1
    for (int c = 0; c < 2; c++) {
        ull acc[NS][8];
        {
            const ulonglong2* bp = (const ulonglong2*)(sb2 + c * 16);
            #pragma unroll
            for (int q = 0; q < 4; q++) {
                const ulonglong2 bv = bp[q];
                #pragma unroll
                for (int s = 0; s < NS; s++) { acc[s][2*q] = bv.x; acc[s][2*q+1] = bv.y; }
            }
        }

        #pragma unroll
        for (int k = 0; k < HID; k++) {
            const ulonglong2* w2r = (const ulonglong2*)(sW2 + k * HID + c * 16);
            const ulonglong2 wv0 = w2r[0];
            const ulonglong2 wv1 = w2r[1];
            const ulonglong2 wv2 = w2r[2];
            const ulonglong2 wv3 = w2r[3];
            #pragma unroll
            for (int s = 0; s < NS; s++) {
                const ull vp = pk2(v[s][k], v[s][k]);
                acc[s][0] = fma2(vp, wv0.x, acc[s][0]);
                acc[s][1] = fma2(vp, wv0.y, acc[s][1]);
                acc[s][2] = fma2(vp, wv1.x, acc[s][2]);
                acc[s][3] = fma2(vp, wv1.y, acc[s][3]);
                acc[s][4] = fma2(vp, wv2.x, acc[s][4]);
                acc[s][5] = fma2(vp, wv2.y, acc[s][5]);
                acc[s][6] = fma2(vp, wv3.x, acc[s][6]);
                acc[s][7] = fma2(vp, wv3.y, acc[s][7]);
            }
        }

        const float* w3c = sW3 + c * 16;
        #pragma unroll
        for (int q = 0; q < 8; q++) {
            const float wl = w3c[2*q];
            const float wh = w3c[2*q+1];
            #pragma unroll
            for (int s = 0; s < NS; s++) {
                float lo, hi;
                upk2(acc[s][q], lo, hi);
                z[s] += fmaxf(lo, 0.0f) * wl;
                z[s] += fmaxf(hi, 0.0f) * wh;
            }
        }
    }

    // ---- sigmoid + stores
    #pragma unroll
    for (int s = 0; s < NS; s++) {
        const int p = p0 + tid + s * THREADS;
        const float o = 0.5f / (1.0f + __expf(-z[s]));
        if (p < NPOS) {
            out[(long)row * TDIM + WSZ + p] = o;
            if (p == 0) {
                #pragma unroll
                for (int c = 0; c < WSZ; c++)
                    out[(long)row * TDIM + c] = o;
            }
        }
    }
}

extern "C" void kernel_launch(void* const* d_in, const int* in_sizes, int n_in,
                              void* d_out, int out_size)
{
    const float* returns = (const float*)d_in[0];
    const float* W1      = (const float*)d_in[1];
    const float* b1      = (const float*)d_in[2];
    const float* W2      = (const float*)d_in[3];
    const float* b2      = (const float*)d_in[4];
    const float* W3      = (const float*)d_in[5];
    const float* b3      = (const float*)d_in[6];
    float* out           = (float*)d_out;

    dim3 grid((NPOS + POS_PER_CTA - 1) / POS_PER_CTA, BDIM); // (8, 1024)
    hurst_mlp_kernel<<<grid, THREADS>>>(returns, W1, b1, W2, b2, W3, b3, out);
}

// round 16
// speedup vs baseline: 10.7628x; 2.6328x over previous
#include <cuda_runtime.h>
#include <cuda_bf16.h>
#include <cstdint>

#define BDIM 1024
#define TDIM 4096
#define WSZ 10
#define HID 32
#define NPOS (TDIM - WSZ)            /* 4086 */
#define THREADS 128
#define ITERS 4
#define POS_PER_CTA 512              /* 4 warps * 32 pos * 4 iters */

static __device__ __forceinline__ uint32_t cvt2(float hi, float lo) {
    uint32_t r;
    asm("cvt.rn.bf16x2.f32 %0, %1, %2;" : "=r"(r) : "f"(hi), "f"(lo));
    return r;
}
static __device__ __forceinline__ uint32_t cvt2relu(float hi, float lo) {
    uint32_t r;
    asm("cvt.rn.relu.bf16x2.f32 %0, %1, %2;" : "=r"(r) : "f"(hi), "f"(lo));
    return r;
}
// D = A(16x16) @ B(16x8) + C, bf16 inputs, f32 accumulate
static __device__ __forceinline__ void mma16816(float* d, const uint32_t* a,
                                                const uint32_t* b, const float* c) {
    asm("mma.sync.aligned.m16n8k16.row.col.f32.bf16.bf16.f32 "
        "{%0,%1,%2,%3}, {%4,%5,%6,%7}, {%8,%9}, {%10,%11,%12,%13};"
        : "=f"(d[0]), "=f"(d[1]), "=f"(d[2]), "=f"(d[3])
        : "r"(a[0]), "r"(a[1]), "r"(a[2]), "r"(a[3]),
          "r"(b[0]), "r"(b[1]),
          "f"(c[0]), "f"(c[1]), "f"(c[2]), "f"(c[3]));
}

__global__ __launch_bounds__(THREADS)
void hurst_mma_kernel(const float* __restrict__ returns,
                      const float* __restrict__ W1, const float* __restrict__ b1,
                      const float* __restrict__ W2, const float* __restrict__ b2,
                      const float* __restrict__ W3, const float* __restrict__ b3,
                      float* __restrict__ out)
{
    __shared__ float sW1[WSZ * HID];     // [k][n]
    __shared__ float sW2[HID * HID];     // [k][n]
    __shared__ float sW3[HID];
    __shared__ float sb1[HID];
    __shared__ float sb2[HID];
    __shared__ float sxs[POS_PER_CTA + WSZ + 4];

    const int tid  = threadIdx.x;
    const int lane = tid & 31;
    const int wid  = tid >> 5;
    const int row  = blockIdx.y;
    const int p0   = blockIdx.x * POS_PER_CTA;

    for (int i = tid; i < WSZ * HID; i += THREADS) sW1[i] = W1[i];
    for (int i = tid; i < HID * HID; i += THREADS) sW2[i] = W2[i];
    if (tid < HID) { sW3[tid] = W3[tid]; sb1[tid] = b1[tid]; sb2[tid] = b2[tid]; }
    const float* xrow = returns + (long)row * TDIM;
    for (int i = tid; i < POS_PER_CTA + WSZ; i += THREADS) {
        int t = p0 + i;
        sxs[i] = (t < TDIM) ? xrow[t] : 0.0f;
    }
    const float bb3 = b3[0];
    __syncthreads();

    const int gq = lane >> 2;   // fragment "group" (row base / B-col)
    const int tq = lane & 3;
    const int kc = tq * 2;      // fragment k/col base

    // ---- persistent B fragments (bf16) + bias/W3 lane values (f32)
    uint32_t B1r[4][2];
    #pragma unroll
    for (int nt = 0; nt < 4; nt++) {
        const int n = nt * 8 + gq;
        B1r[nt][0] = cvt2(sW1[(kc + 1) * HID + n], sW1[kc * HID + n]);   // k rows kc,kc+1 (<8)
        const float lo2 = (kc + 8 < WSZ) ? sW1[(kc + 8) * HID + n] : 0.0f;
        const float hi2 = (kc + 9 < WSZ) ? sW1[(kc + 9) * HID + n] : 0.0f;
        B1r[nt][1] = cvt2(hi2, lo2);                                     // k rows kc+8,kc+9 (pad 0)
    }
    uint32_t B2r[2][4][2];
    #pragma unroll
    for (int kt = 0; kt < 2; kt++) {
        #pragma unroll
        for (int nt = 0; nt < 4; nt++) {
            const int n = nt * 8 + gq;
            const int k = kt * 16 + kc;
            B2r[kt][nt][0] = cvt2(sW2[(k + 1) * HID + n], sW2[k * HID + n]);
            B2r[kt][nt][1] = cvt2(sW2[(k + 9) * HID + n], sW2[(k + 8) * HID + n]);
        }
    }
    float c1lo[4], c1hi[4], c2lo[4], c2hi[4], w3lo[4], w3hi[4];
    #pragma unroll
    for (int nt = 0; nt < 4; nt++) {
        const int nn = nt * 8 + kc;      // D/C fragment column for this lane
        c1lo[nt] = sb1[nn];  c1hi[nt] = sb1[nn + 1];
        c2lo[nt] = sb2[nn];  c2hi[nt] = sb2[nn + 1];
        w3lo[nt] = sW3[nn];  w3hi[nt] = sW3[nn + 1];
    }

    #pragma unroll 1
    for (int it = 0; it < ITERS; it++) {
        const int pb = it * 128 + wid * 32;     // warp tile base (CTA-local)

        // ---- A1 fragments: window matrix X[32 x 16] (k<10 real, rest 0)
        uint32_t A1r[2][4];
        #pragma unroll
        for (int t = 0; t < 2; t++) {
            const int base = pb + t * 16 + gq;
            const float x0 = sxs[base + kc],     x1 = sxs[base + kc + 1];
            const float x2 = sxs[base + 8 + kc], x3 = sxs[base + 8 + kc + 1];
            A1r[t][0] = cvt2(x1, x0);            // (row, kc..kc+1)
            A1r[t][1] = cvt2(x3, x2);            // (row+8, kc..kc+1)
            float y0 = 0.f, y1 = 0.f, y2 = 0.f, y3 = 0.f;
            if (tq == 0) {                       // cols 8,9 only (10..15 are pad)
                y0 = sxs[base + 8];  y1 = sxs[base + 9];
                y2 = sxs[base + 16]; y3 = sxs[base + 17];
            }
            A1r[t][2] = cvt2(y1, y0);            // (row, kc+8..)
            A1r[t][3] = cvt2(y3, y2);            // (row+8, kc+8..)
        }

        // ---- layer 1 MMA (bias in C) + fused relu/cvt into A2 fragments
        uint32_t A2r[2][2][4];
        #pragma unroll
        for (int t = 0; t < 2; t++) {
            #pragma unroll
            for (int kt = 0; kt < 2; kt++) {
                float d0[4], d1[4];
                const float ci0[4] = {c1lo[2*kt],   c1hi[2*kt],   c1lo[2*kt],   c1hi[2*kt]};
                const float ci1[4] = {c1lo[2*kt+1], c1hi[2*kt+1], c1lo[2*kt+1], c1hi[2*kt+1]};
                mma16816(d0, A1r[t], B1r[2*kt],     ci0);
                mma16816(d1, A1r[t], B1r[2*kt + 1], ci1);
                A2r[t][kt][0] = cvt2relu(d0[1], d0[0]);
                A2r[t][kt][1] = cvt2relu(d0[3], d0[2]);
                A2r[t][kt][2] = cvt2relu(d1[1], d1[0]);
                A2r[t][kt][3] = cvt2relu(d1[3], d1[2]);
            }
        }

        // ---- layer 2 MMA (bias in C, K=32 over 2 k-tiles) + layer-3 dot
        float s00 = 0.f, s01 = 0.f, s10 = 0.f, s11 = 0.f;
        #pragma unroll
        for (int t = 0; t < 2; t++) {
            #pragma unroll
            for (int nt = 0; nt < 4; nt++) {
                float d[4];
                const float ci[4] = {c2lo[nt], c2hi[nt], c2lo[nt], c2hi[nt]};
                mma16816(d, A2r[t][0], B2r[0][nt], ci);
                mma16816(d, A2r[t][1], B2r[1][nt], d);
                const float r0 = fmaxf(d[0], 0.f), r1 = fmaxf(d[1], 0.f);
                const float r2 = fmaxf(d[2], 0.f), r3 = fmaxf(d[3], 0.f);
                if (t == 0) {
                    s00 += r0 * w3lo[nt] + r1 * w3hi[nt];
                    s01 += r2 * w3lo[nt] + r3 * w3hi[nt];
                } else {
                    s10 += r0 * w3lo[nt] + r1 * w3hi[nt];
                    s11 += r2 * w3lo[nt] + r3 * w3hi[nt];
                }
            }
        }

        // ---- reduce partial dot over the 4 lanes sharing each row
        s00 += __shfl_xor_sync(0xFFFFFFFFu, s00, 1);
        s00 += __shfl_xor_sync(0xFFFFFFFFu, s00, 2);
        s01 += __shfl_xor_sync(0xFFFFFFFFu, s01, 1);
        s01 += __shfl_xor_sync(0xFFFFFFFFu, s01, 2);
        s10 += __shfl_xor_sync(0xFFFFFFFFu, s10, 1);
        s10 += __shfl_xor_sync(0xFFFFFFFFu, s10, 2);
        s11 += __shfl_xor_sync(0xFFFFFFFFu, s11, 1);
        s11 += __shfl_xor_sync(0xFFFFFFFFu, s11, 2);

        // lane tq handles row offset tq*8: {s00,s01,s10,s11}[tq]
        float zsel = (tq & 2) ? ((tq & 1) ? s11 : s10)
                              : ((tq & 1) ? s01 : s00);
        const float z = zsel + bb3;
        const int p = p0 + pb + gq + tq * 8;
        const float o = 0.5f / (1.0f + __expf(-z));
        if (p < NPOS) {
            out[(long)row * TDIM + WSZ + p] = o;
            if (p == 0) {
                #pragma unroll
                for (int cc = 0; cc < WSZ; cc++)
                    out[(long)row * TDIM + cc] = o;
            }
        }
    }
}

extern "C" void kernel_launch(void* const* d_in, const int* in_sizes, int n_in,
                              void* d_out, int out_size)
{
    const float* returns = (const float*)d_in[0];
    const float* W1      = (const float*)d_in[1];
    const float* b1      = (const float*)d_in[2];
    const float* W2      = (const float*)d_in[3];
    const float* b2      = (const float*)d_in[4];
    const float* W3      = (const float*)d_in[5];
    const float* b3      = (const float*)d_in[6];
    float* out           = (float*)d_out;

    dim3 grid((NPOS + POS_PER_CTA - 1) / POS_PER_CTA, BDIM); // (8, 1024)
    hurst_mma_kernel<<<grid, THREADS>>>(returns, W1, b1, W2, b2, W3, b3, out);
}